// round 2
// baseline (speedup 1.0000x reference)
#include <cuda_runtime.h>
#include <math.h>

// Problem dims (fixed per reference)
#define BROWS   4096
#define IN_DIM  1024
#define X_DIM   2048
#define OUT_DIM 512
#define ZLAYERS 6

// Scratch: 7 activation buffers of [4096, 2048] fp32 (224 MB, static device mem)
__device__ float g_buf[7ull * BROWS * X_DIM];

// GEMM tiling
#define BM 128
#define BN 128
#define BK 16
#define TM 8
#define TN 8

__device__ __forceinline__ float activate(float v, int a, float mo) {
    float r;
    if (a == 0) {
        r = fmaxf(v, 0.0f);                       // relu
    } else if (a == 1) {
        r = 1.0f / (1.0f + expf(-v));             // sigmoid
    } else if (a == 2) {
        r = tanhf(v);                             // tanh
    } else if (a == 3) {
        r = (v >= 0.0f) ? v : 0.1f * v;           // leaky relu(0.1)
    } else {
        const float sc = 1.0507009873554805f;     // selu
        const float al = 1.6732632423543772f;
        r = (v > 0.0f) ? sc * v : sc * al * expm1f(v);
    }
    return fminf(r, mo);
}

// C[M, N] = act( [A1 | A2] @ W + bias ), A row-major, W row-major [K, N].
// A1 has K1 cols (stride K1); A2 (optional) has K2 cols (stride K2).
// All dims multiples of the tile sizes (checked against problem constants).
__global__ __launch_bounds__(256, 2)
void gemm_act_kernel(const float* __restrict__ A1,
                     const float* __restrict__ A2,
                     int K1, int K2,
                     const float* __restrict__ W,
                     const float* __restrict__ bias,
                     const float* __restrict__ mo,
                     const int*   __restrict__ aid,
                     float* __restrict__ C,
                     int Ntot) {
    __shared__ float As[BK][BM];
    __shared__ float Bs[BK][BN];

    const int tid     = threadIdx.x;            // 0..255
    const int block_m = blockIdx.y * BM;
    const int block_n = blockIdx.x * BN;
    const int trow    = (tid / 16) * TM;        // 0..120
    const int tcol    = (tid % 16) * TN;        // 0..120

    float acc[TM][TN];
#pragma unroll
    for (int i = 0; i < TM; i++)
#pragma unroll
        for (int j = 0; j < TN; j++) acc[i][j] = 0.0f;

    const int Ktot = K1 + K2;

    for (int k0 = 0; k0 < Ktot; k0 += BK) {
        // Select A source for this K-tile (K1 is a multiple of BK, so a tile
        // never straddles the concat boundary).
        const float* Asrc;
        int lda, kk;
        if (k0 < K1) { Asrc = A1; lda = K1; kk = k0; }
        else         { Asrc = A2; lda = K2; kk = k0 - K1; }

        // Load A tile: 128 rows x 16 cols = 512 float4, 2 per thread,
        // stored transposed As[k][m] for broadcast-friendly reads.
#pragma unroll
        for (int i = 0; i < 2; i++) {
            int f   = tid + i * 256;
            int row = f >> 2;             // 0..127
            int kq  = (f & 3) * 4;        // 0,4,8,12
            float4 v = *reinterpret_cast<const float4*>(
                Asrc + (size_t)(block_m + row) * lda + kk + kq);
            As[kq + 0][row] = v.x;
            As[kq + 1][row] = v.y;
            As[kq + 2][row] = v.z;
            As[kq + 3][row] = v.w;
        }
        // Load W tile: 16 rows x 128 cols = 512 float4, 2 per thread.
#pragma unroll
        for (int i = 0; i < 2; i++) {
            int f    = tid + i * 256;
            int krow = f >> 5;            // 0..15
            int nq   = (f & 31) * 4;      // 0..124
            float4 v = *reinterpret_cast<const float4*>(
                W + (size_t)(k0 + krow) * Ntot + block_n + nq);
            *reinterpret_cast<float4*>(&Bs[krow][nq]) = v;
        }
        __syncthreads();

#pragma unroll
        for (int k = 0; k < BK; k++) {
            float a[TM], b[TN];
#pragma unroll
            for (int i = 0; i < TM; i++) a[i] = As[k][trow + i];
#pragma unroll
            for (int j = 0; j < TN; j++) b[j] = Bs[k][tcol + j];
#pragma unroll
            for (int i = 0; i < TM; i++)
#pragma unroll
                for (int j = 0; j < TN; j++)
                    acc[i][j] = fmaf(a[i], b[j], acc[i][j]);
        }
        __syncthreads();
    }

    // Fused epilogue: bias + per-column activation select + clip
#pragma unroll
    for (int j = 0; j < TN; j++) {
        int   n   = block_n + tcol + j;
        float bj  = bias[n];
        float moj = mo[n];
        int   aj  = aid[n];
#pragma unroll
        for (int i = 0; i < TM; i++) {
            float v = acc[i][j] + bj;
            C[(size_t)(block_m + trow + i) * Ntot + n] = activate(v, aj, moj);
        }
    }
}

extern "C" void kernel_launch(void* const* d_in, const int* in_sizes, int n_in,
                              void* d_out, int out_size) {
    const float* x     = (const float*)d_in[0];
    const float* W_in  = (const float*)d_in[1];
    const float* b_in  = (const float*)d_in[2];
    const float* Wh[ZLAYERS] = {
        (const float*)d_in[3], (const float*)d_in[4], (const float*)d_in[5],
        (const float*)d_in[6], (const float*)d_in[7], (const float*)d_in[8]
    };
    const float* bh    = (const float*)d_in[9];
    const float* W_out = (const float*)d_in[10];
    const float* b_out = (const float*)d_in[11];
    const float* mo_in = (const float*)d_in[12];
    const float* mo_h  = (const float*)d_in[13];
    const float* mo_out= (const float*)d_in[14];
    const int*   aid_in = (const int*)d_in[15];
    const int*   aid_h  = (const int*)d_in[16];
    const int*   aid_out= (const int*)d_in[17];
    float* out = (float*)d_out;

    float* buf = nullptr;
    cudaGetSymbolAddress((void**)&buf, g_buf);

    const size_t SZ = (size_t)BROWS * X_DIM;
    auto O = [&](int i) { return buf + (size_t)i * SZ; };

    dim3 blk(256);
    dim3 gridX(X_DIM / BN, BROWS / BM);    // hidden layers: 16 x 32
    dim3 gridO(OUT_DIM / BN, BROWS / BM);  // output layer:   4 x 32

    // Input layer: o0 = act(x @ W_in + b_in)
    gemm_act_kernel<<<gridX, blk>>>(x, nullptr, IN_DIM, 0,
                                    W_in, b_in, mo_in, aid_in, O(0), X_DIM);
    // RES = [F, F, 1, F, 3, F]; outs[] indexing: outs[0]=o0 ... outs[i+1]=O(i+1)
    // layer 0: t = outs[0]
    gemm_act_kernel<<<gridX, blk>>>(O(0), nullptr, X_DIM, 0,
                                    Wh[0], bh + 0 * X_DIM, mo_h + 0 * X_DIM,
                                    aid_h + 0 * X_DIM, O(1), X_DIM);
    // layer 1: t = outs[1]
    gemm_act_kernel<<<gridX, blk>>>(O(1), nullptr, X_DIM, 0,
                                    Wh[1], bh + 1 * X_DIM, mo_h + 1 * X_DIM,
                                    aid_h + 1 * X_DIM, O(2), X_DIM);
    // layer 2: t = concat(outs[2], outs[1])
    gemm_act_kernel<<<gridX, blk>>>(O(2), O(1), X_DIM, X_DIM,
                                    Wh[2], bh + 2 * X_DIM, mo_h + 2 * X_DIM,
                                    aid_h + 2 * X_DIM, O(3), X_DIM);
    // layer 3: t = outs[3]
    gemm_act_kernel<<<gridX, blk>>>(O(3), nullptr, X_DIM, 0,
                                    Wh[3], bh + 3 * X_DIM, mo_h + 3 * X_DIM,
                                    aid_h + 3 * X_DIM, O(4), X_DIM);
    // layer 4: t = concat(outs[4], outs[3])
    gemm_act_kernel<<<gridX, blk>>>(O(4), O(3), X_DIM, X_DIM,
                                    Wh[4], bh + 4 * X_DIM, mo_h + 4 * X_DIM,
                                    aid_h + 4 * X_DIM, O(5), X_DIM);
    // layer 5: t = outs[5]
    gemm_act_kernel<<<gridX, blk>>>(O(5), nullptr, X_DIM, 0,
                                    Wh[5], bh + 5 * X_DIM, mo_h + 5 * X_DIM,
                                    aid_h + 5 * X_DIM, O(6), X_DIM);
    // Output layer: out = act(outs[6] @ W_out + b_out)
    gemm_act_kernel<<<gridO, blk>>>(O(6), nullptr, X_DIM, 0,
                                    W_out, b_out, mo_out, aid_out, out, OUT_DIM);
}